// round 11
// baseline (speedup 1.0000x reference)
#include <cuda_runtime.h>
#include <cuda_bf16.h>
#include <cstdint>

// ---------------------------------------------------------------------------
// QGCN forward on GB300 — CSR gather + split-BF16 TC GEMM.
// Gather->GEMM boundaries chunk-pipelined across two streams.
// Buffers ping-pong (A/D) so overlapping kernels never alias.
// ---------------------------------------------------------------------------

#define N_NODES 50000
#define N_EDGES 800000
#define NCHUNK 4

__device__ float  g_bufA[N_NODES * 128];
__device__ float  g_bufB[N_NODES * 128];
__device__ float  g_bufC[N_NODES * 128];
__device__ float  g_bufD[N_NODES * 128];
__device__ int    g_deg[N_NODES];
__device__ int    g_indptr[N_NODES + 1];
__device__ int    g_cursor[N_NODES];
__device__ float2 g_edges[N_EDGES];   // {src (bit-cast int), weight}

// ---------------------------------------------------------------------------
// BF16 helpers
// ---------------------------------------------------------------------------
__device__ __forceinline__ uint32_t pack_bf16x2(__nv_bfloat16 lo16, __nv_bfloat16 hi16) {
    __nv_bfloat162 t;
    t.x = lo16;
    t.y = hi16;
    return *reinterpret_cast<uint32_t*>(&t);
}
__device__ __forceinline__ void split_pair(float a, float b,
                                           uint32_t& wh, uint32_t& wl) {
    __nv_bfloat16 ah = __float2bfloat16_rn(a);
    __nv_bfloat16 bh = __float2bfloat16_rn(b);
    __nv_bfloat16 al = __float2bfloat16_rn(a - __bfloat162float(ah));
    __nv_bfloat16 bl = __float2bfloat16_rn(b - __bfloat162float(bh));
    wh = pack_bf16x2(ah, bh);
    wl = pack_bf16x2(al, bl);
}
__device__ __forceinline__ void mma_bf16(
    float& d0, float& d1, float& d2, float& d3,
    uint32_t a0, uint32_t a1, uint32_t a2, uint32_t a3,
    uint32_t b0, uint32_t b1)
{
    asm volatile(
        "mma.sync.aligned.m16n8k16.row.col.f32.bf16.bf16.f32 "
        "{%0,%1,%2,%3},{%4,%5,%6,%7},{%8,%9},{%0,%1,%2,%3};"
        : "+f"(d0), "+f"(d1), "+f"(d2), "+f"(d3)
        : "r"(a0), "r"(a1), "r"(a2), "r"(a3), "r"(b0), "r"(b1));
}

// ---------------------------------------------------------------------------
// GEMM: Y[rows row_off.., BNT] = X @ W   (R7 inner loop + row offset)
// ---------------------------------------------------------------------------
template <int BNT>
__global__ __launch_bounds__(128, 4) void gemm_tc_kernel(
    const float* __restrict__ X, const float* __restrict__ W,
    float* __restrict__ Y, int N, int row_off)
{
    constexpr int KC   = 32;
    constexpr int NK   = 128 / KC;
    constexpr int XSPW = 20;
    constexpr int WSPW = 72;

    __shared__ uint32_t Xh[64][XSPW], Xl[64][XSPW];
    __shared__ uint32_t Wh[16][WSPW], Wl[16][WSPW];

    const int tid  = threadIdx.x;
    const int lane = tid & 31;
    const int warp = tid >> 5;
    const int row0 = row_off + blockIdx.x * 64;
    const int nb   = blockIdx.y * 64;

    const int qr = lane >> 2;
    const int qt = lane & 3;
    const int wm = (warp & 1) * 32;
    const int wn = (warp >> 1) * 32;

    const float4* X4 = (const float4*)X;
    const float4* W4 = (const float4*)W;

    float4 xr[4];
    float4 wrA[2], wrB[2];

    auto ldgX = [&](int ch) {
#pragma unroll
        for (int i = 0; i < 4; i++) {
            int idx = tid + i * 128;
            int r = idx >> 3, c4 = idx & 7;
            int gr = row0 + r;
            xr[i] = (gr < N) ? X4[gr * 32 + ch * 8 + c4]
                             : make_float4(0.f, 0.f, 0.f, 0.f);
        }
    };
    auto ldgW = [&](int ch) {
#pragma unroll
        for (int i = 0; i < 2; i++) {
            int idx = tid + i * 128;
            int kp = idx >> 4, cc = idx & 15;
            wrA[i] = W4[(((ch * KC + 2 * kp)     * BNT + nb) >> 2) + cc];
            wrB[i] = W4[(((ch * KC + 2 * kp + 1) * BNT + nb) >> 2) + cc];
        }
    };
    auto stsX = [&]() {
#pragma unroll
        for (int i = 0; i < 4; i++) {
            int idx = tid + i * 128;
            int r = idx >> 3, c4 = idx & 7;
            uint32_t h0, l0, h1, l1;
            split_pair(xr[i].x, xr[i].y, h0, l0);
            split_pair(xr[i].z, xr[i].w, h1, l1);
            Xh[r][c4 * 2 + 0] = h0;  Xl[r][c4 * 2 + 0] = l0;
            Xh[r][c4 * 2 + 1] = h1;  Xl[r][c4 * 2 + 1] = l1;
        }
    };
    auto stsW = [&]() {
#pragma unroll
        for (int i = 0; i < 2; i++) {
            int idx = tid + i * 128;
            int kp = idx >> 4, cc = idx & 15;
            const float* a = (const float*)&wrA[i];
            const float* b = (const float*)&wrB[i];
#pragma unroll
            for (int j = 0; j < 4; j++) {
                uint32_t wh, wl;
                split_pair(a[j], b[j], wh, wl);
                Wh[kp][cc * 4 + j] = wh;
                Wl[kp][cc * 4 + j] = wl;
            }
        }
    };

    float acc[2][4][4] = {};

    ldgX(0); ldgW(0);
    stsX(); stsW();
    __syncthreads();

#pragma unroll
    for (int ch = 0; ch < NK; ch++) {
        if (ch + 1 < NK) { ldgX(ch + 1); ldgW(ch + 1); }

#pragma unroll
        for (int ks = 0; ks < 2; ks++) {
            const int kw = ks * 8 + qt;

            uint32_t ahi[2][4], alo[2][4];
#pragma unroll
            for (int mt = 0; mt < 2; mt++) {
                int r = wm + mt * 16 + qr;
                ahi[mt][0] = Xh[r][kw];
                ahi[mt][1] = Xh[r + 8][kw];
                ahi[mt][2] = Xh[r][kw + 4];
                ahi[mt][3] = Xh[r + 8][kw + 4];
                alo[mt][0] = Xl[r][kw];
                alo[mt][1] = Xl[r + 8][kw];
                alo[mt][2] = Xl[r][kw + 4];
                alo[mt][3] = Xl[r + 8][kw + 4];
            }
            uint32_t bhi[4][2], blo[4][2];
#pragma unroll
            for (int nt = 0; nt < 4; nt++) {
                int c = wn + nt * 8 + qr;
                bhi[nt][0] = Wh[ks * 8 + qt][c];
                bhi[nt][1] = Wh[ks * 8 + qt + 4][c];
                blo[nt][0] = Wl[ks * 8 + qt][c];
                blo[nt][1] = Wl[ks * 8 + qt + 4][c];
            }
#pragma unroll
            for (int mt = 0; mt < 2; mt++)
#pragma unroll
                for (int nt = 0; nt < 4; nt++) {
                    float* d = acc[mt][nt];
                    mma_bf16(d[0], d[1], d[2], d[3],
                             ahi[mt][0], ahi[mt][1], ahi[mt][2], ahi[mt][3],
                             bhi[nt][0], bhi[nt][1]);
                    mma_bf16(d[0], d[1], d[2], d[3],
                             ahi[mt][0], ahi[mt][1], ahi[mt][2], ahi[mt][3],
                             blo[nt][0], blo[nt][1]);
                    mma_bf16(d[0], d[1], d[2], d[3],
                             alo[mt][0], alo[mt][1], alo[mt][2], alo[mt][3],
                             bhi[nt][0], bhi[nt][1]);
                }
        }

        if (ch + 1 < NK) {
            __syncthreads();
            stsX(); stsW();
            __syncthreads();
        }
    }

#pragma unroll
    for (int mt = 0; mt < 2; mt++) {
#pragma unroll
        for (int nt = 0; nt < 4; nt++) {
            int gc = nb + wn + nt * 8 + qt * 2;
            int r0g = row0 + wm + mt * 16 + qr;
            if (r0g < N)
                *(float2*)&Y[r0g * BNT + gc] =
                    make_float2(acc[mt][nt][0], acc[mt][nt][1]);
            int r1g = r0g + 8;
            if (r1g < N)
                *(float2*)&Y[r1g * BNT + gc] =
                    make_float2(acc[mt][nt][2], acc[mt][nt][3]);
        }
    }
}

// ---------------------------------------------------------------------------
// CSR build
// ---------------------------------------------------------------------------
__global__ __launch_bounds__(256) void hist_kernel(
    const int* __restrict__ dst, int* __restrict__ deg, int E)
{
    int e = blockIdx.x * blockDim.x + threadIdx.x;
    if (e < E) atomicAdd(&deg[__ldg(&dst[e])], 1);
}

__global__ __launch_bounds__(1024) void scan_kernel(
    const int* __restrict__ deg, int* __restrict__ indptr,
    int* __restrict__ cursor)
{
    __shared__ int sh[1024];
    const int CHUNK = (N_NODES + 1023) / 1024;
    int t = threadIdx.x;
    int begin = t * CHUNK;
    int end   = begin + CHUNK; if (end > N_NODES) end = N_NODES;

    int s = 0;
    for (int i = begin; i < end; i++) s += deg[i];
    sh[t] = s;
    __syncthreads();

    for (int off = 1; off < 1024; off <<= 1) {
        int v = sh[t];
        int a = (t >= off) ? sh[t - off] : 0;
        __syncthreads();
        sh[t] = v + a;
        __syncthreads();
    }

    int run = (t == 0) ? 0 : sh[t - 1];
    for (int i = begin; i < end; i++) {
        indptr[i] = run;
        cursor[i] = run;
        run += deg[i];
    }
    if (t == 1023) indptr[N_NODES] = run;
}

__global__ __launch_bounds__(256) void place_kernel(
    const int* __restrict__ src, const int* __restrict__ dst,
    const float* __restrict__ ew, int* __restrict__ cursor,
    float2* __restrict__ edges, int E)
{
    int e = blockIdx.x * blockDim.x + threadIdx.x;
    if (e >= E) return;
    int d = __ldg(&dst[e]);
    int p = atomicAdd(&cursor[d], 1);
    edges[p] = make_float2(__int_as_float(__ldg(&src[e])), __ldg(&ew[e]));
}

// ---------------------------------------------------------------------------
// Gather-aggregate, D=128: one warp per dst node (node range [off, end)).
// MODE 0: val=acc+b; out0=val; out1=val+relu(val)    (layer 0)
// MODE 1: val=acc+b; out0=Bres+relu(val)             (layer 1)
// ---------------------------------------------------------------------------
template <int MODE>
__global__ __launch_bounds__(256) void gather128_kernel(
    const float* __restrict__ H, const float2* __restrict__ edges,
    const int* __restrict__ indptr,
    const float* __restrict__ bias, const float* __restrict__ Bres,
    float* __restrict__ out0, float* __restrict__ out1,
    int node_off, int node_end)
{
    int node = node_off + ((blockIdx.x * 256 + threadIdx.x) >> 5);
    int lane = threadIdx.x & 31;
    if (node >= node_end) return;

    int start = __ldg(&indptr[node]);
    int endp  = __ldg(&indptr[node + 1]);
    int cnt   = endp - start;
    int last  = endp - 1;

    float4 acc = make_float4(0.f, 0.f, 0.f, 0.f);
    const float4* H4 = (const float4*)H;

    if (cnt > 0) {
        float2 e0 = __ldg(&edges[start]);
        float2 e1 = __ldg(&edges[min(start + 1, last)]);
        int j = 0;
        for (; j + 1 < cnt; j += 2) {
            float2 n0 = __ldg(&edges[min(start + j + 2, last)]);
            float2 n1 = __ldg(&edges[min(start + j + 3, last)]);
            float4 v0 = __ldg(&H4[(__float_as_int(e0.x) << 5) + lane]);
            float4 v1 = __ldg(&H4[(__float_as_int(e1.x) << 5) + lane]);
            acc.x = fmaf(v0.x, e0.y, acc.x); acc.y = fmaf(v0.y, e0.y, acc.y);
            acc.z = fmaf(v0.z, e0.y, acc.z); acc.w = fmaf(v0.w, e0.y, acc.w);
            acc.x = fmaf(v1.x, e1.y, acc.x); acc.y = fmaf(v1.y, e1.y, acc.y);
            acc.z = fmaf(v1.z, e1.y, acc.z); acc.w = fmaf(v1.w, e1.y, acc.w);
            e0 = n0; e1 = n1;
        }
        if (j < cnt) {
            float4 v0 = __ldg(&H4[(__float_as_int(e0.x) << 5) + lane]);
            acc.x = fmaf(v0.x, e0.y, acc.x); acc.y = fmaf(v0.y, e0.y, acc.y);
            acc.z = fmaf(v0.z, e0.y, acc.z); acc.w = fmaf(v0.w, e0.y, acc.w);
        }
    }

    float4 bb = ((const float4*)bias)[lane];
    float4 val = make_float4(acc.x + bb.x, acc.y + bb.y,
                             acc.z + bb.z, acc.w + bb.w);
    int idx = (node << 5) + lane;

    if (MODE == 0) {
        ((float4*)out0)[idx] = val;
        float4 c;
        c.x = val.x + fmaxf(val.x, 0.f); c.y = val.y + fmaxf(val.y, 0.f);
        c.z = val.z + fmaxf(val.z, 0.f); c.w = val.w + fmaxf(val.w, 0.f);
        ((float4*)out1)[idx] = c;
    } else {
        float4 b = __ldg(&((const float4*)Bres)[idx]);
        float4 c;
        c.x = b.x + fmaxf(val.x, 0.f); c.y = b.y + fmaxf(val.y, 0.f);
        c.z = b.z + fmaxf(val.z, 0.f); c.w = b.w + fmaxf(val.w, 0.f);
        ((float4*)out0)[idx] = c;
    }
}

// D=64: half-warp per node.
__global__ __launch_bounds__(256) void gather64_kernel(
    const float* __restrict__ H, const float2* __restrict__ edges,
    const int* __restrict__ indptr,
    const float* __restrict__ bias, float* __restrict__ out)
{
    int node = (blockIdx.x * 256 + threadIdx.x) >> 4;
    int lane = threadIdx.x & 15;
    if (node >= N_NODES) return;

    int start = __ldg(&indptr[node]);
    int endp  = __ldg(&indptr[node + 1]);
    int cnt   = endp - start;
    int last  = endp - 1;

    float4 acc = make_float4(0.f, 0.f, 0.f, 0.f);
    const float4* H4 = (const float4*)H;

    if (cnt > 0) {
        float2 e0 = __ldg(&edges[start]);
        float2 e1 = __ldg(&edges[min(start + 1, last)]);
        int j = 0;
        for (; j + 1 < cnt; j += 2) {
            float2 n0 = __ldg(&edges[min(start + j + 2, last)]);
            float2 n1 = __ldg(&edges[min(start + j + 3, last)]);
            float4 v0 = __ldg(&H4[(__float_as_int(e0.x) << 4) + lane]);
            float4 v1 = __ldg(&H4[(__float_as_int(e1.x) << 4) + lane]);
            acc.x = fmaf(v0.x, e0.y, acc.x); acc.y = fmaf(v0.y, e0.y, acc.y);
            acc.z = fmaf(v0.z, e0.y, acc.z); acc.w = fmaf(v0.w, e0.y, acc.w);
            acc.x = fmaf(v1.x, e1.y, acc.x); acc.y = fmaf(v1.y, e1.y, acc.y);
            acc.z = fmaf(v1.z, e1.y, acc.z); acc.w = fmaf(v1.w, e1.y, acc.w);
            e0 = n0; e1 = n1;
        }
        if (j < cnt) {
            float4 v0 = __ldg(&H4[(__float_as_int(e0.x) << 4) + lane]);
            acc.x = fmaf(v0.x, e0.y, acc.x); acc.y = fmaf(v0.y, e0.y, acc.y);
            acc.z = fmaf(v0.z, e0.y, acc.z); acc.w = fmaf(v0.w, e0.y, acc.w);
        }
    }

    float4 bb = ((const float4*)bias)[lane];
    ((float4*)out)[(node << 4) + lane] =
        make_float4(acc.x + bb.x, acc.y + bb.y, acc.z + bb.z, acc.w + bb.w);
}

// ---------------------------------------------------------------------------

extern "C" void kernel_launch(void* const* d_in, const int* in_sizes, int n_in,
                              void* d_out, int out_size)
{
    const float* x  = (const float*)d_in[0];
    const int*   ei = (const int*)d_in[1];
    const float* ea = (const float*)d_in[2];
    const float* W1 = (const float*)d_in[3];
    const float* b1 = (const float*)d_in[4];
    const float* W2 = (const float*)d_in[5];
    const float* b2 = (const float*)d_in[6];
    const float* W3 = (const float*)d_in[7];
    const float* b3 = (const float*)d_in[8];
    float* out = (float*)d_out;

    const int N = N_NODES;
    const int E = N_EDGES;
    const int* src = ei;
    const int* dst = ei + E;

    float *A, *B, *C, *D;
    int *deg, *indptr, *cursor;
    float2* edges;
    cudaGetSymbolAddress((void**)&A, g_bufA);
    cudaGetSymbolAddress((void**)&B, g_bufB);
    cudaGetSymbolAddress((void**)&C, g_bufC);
    cudaGetSymbolAddress((void**)&D, g_bufD);
    cudaGetSymbolAddress((void**)&deg, g_deg);
    cudaGetSymbolAddress((void**)&indptr, g_indptr);
    cudaGetSymbolAddress((void**)&cursor, g_cursor);
    cudaGetSymbolAddress((void**)&edges, g_edges);

    const int e_blocks = (E + 255) / 256;
    const int mrows    = (N + 63) / 64;          // 782 tiles

    // Chunk partition (tile-aligned)
    int tilesPer = (mrows + NCHUNK - 1) / NCHUNK;          // 196
    int tile0[NCHUNK], tcnt[NCHUNK], n0[NCHUNK], n1[NCHUNK];
    for (int c = 0; c < NCHUNK; c++) {
        tile0[c] = c * tilesPer;
        tcnt[c]  = min(tilesPer, mrows - tile0[c]);
        n0[c]    = tile0[c] * 64;
        n1[c]    = min(N, n0[c] + tcnt[c] * 64);
    }

    // Streams / events (host objects, per call)
    cudaStream_t s2;
    cudaStreamCreateWithFlags(&s2, cudaStreamNonBlocking);
    cudaEvent_t evFork, evG0, evG1, evA[NCHUNK], evB[NCHUNK];
    cudaEventCreateWithFlags(&evFork, cudaEventDisableTiming);
    cudaEventCreateWithFlags(&evG0, cudaEventDisableTiming);
    cudaEventCreateWithFlags(&evG1, cudaEventDisableTiming);
    for (int c = 0; c < NCHUNK; c++) {
        cudaEventCreateWithFlags(&evA[c], cudaEventDisableTiming);
        cudaEventCreateWithFlags(&evB[c], cudaEventDisableTiming);
    }

    // --- Fork: CSR build on s2 ∥ GEMM0 on main ---
    cudaEventRecord(evFork, 0);
    cudaStreamWaitEvent(s2, evFork, 0);

    cudaMemsetAsync(deg, 0, N * sizeof(int), s2);
    hist_kernel<<<e_blocks, 256, 0, s2>>>(dst, deg, E);
    scan_kernel<<<1, 1024, 0, s2>>>(deg, indptr, cursor);
    place_kernel<<<e_blocks, 256, 0, s2>>>(src, dst, ea, cursor, edges, E);

    gemm_tc_kernel<128><<<dim3(mrows, 2), 128>>>(x, W1, A, N, 0);   // main -> A
    cudaEventRecord(evG0, 0);
    cudaStreamWaitEvent(s2, evG0, 0);   // gathers need full GEMM0 (+CSR, s2 order)

    // --- gather0 (s2, chunked; reads A, writes B,C) ∥ gemm1 chunks (main; reads C done-chunks, writes D) ---
    for (int c = 0; c < NCHUNK; c++) {
        int blocks = ((n1[c] - n0[c]) * 32 + 255) / 256;
        gather128_kernel<0><<<blocks, 256, 0, s2>>>(A, edges, indptr, b1,
                                                    nullptr, B, C, n0[c], n1[c]);
        cudaEventRecord(evA[c], s2);
    }
    for (int c = 0; c < NCHUNK; c++) {
        cudaStreamWaitEvent(0, evA[c], 0);
        gemm_tc_kernel<128><<<dim3(tcnt[c], 2), 128>>>(C, W2, D, N, n0[c]);
    }
    cudaEventRecord(evG1, 0);
    cudaStreamWaitEvent(s2, evG1, 0);   // gather1 needs full GEMM1

    // --- gather1 (s2, chunked; reads D,B, writes C) ∥ gemm2 chunks (main; reads C done-chunks, writes A) ---
    for (int c = 0; c < NCHUNK; c++) {
        int blocks = ((n1[c] - n0[c]) * 32 + 255) / 256;
        gather128_kernel<1><<<blocks, 256, 0, s2>>>(D, edges, indptr, b2,
                                                    B, C, nullptr, n0[c], n1[c]);
        cudaEventRecord(evB[c], s2);
    }
    for (int c = 0; c < NCHUNK; c++) {
        cudaStreamWaitEvent(0, evB[c], 0);
        gemm_tc_kernel<64><<<dim3(tcnt[c], 1), 128>>>(C, W3, A, N, n0[c]);
    }

    // --- Final gather (main stream; GEMM2 complete in-order; reads A) ---
    gather64_kernel<<<(N * 16 + 255) / 256, 256>>>(A, edges, indptr, b3, out);
}

// round 12
// speedup vs baseline: 1.3941x; 1.3941x over previous
#include <cuda_runtime.h>
#include <cuda_fp16.h>
#include <cstdint>

// ---------------------------------------------------------------------------
// QGCN forward on GB300 — fp16 intermediate features.
//   GEMM: single-pass mma.sync.m16n8k16.f16 (fp32 accum).
//   Gathers read/write fp16 rows (half the L2 traffic of fp32).
//   CSR build forked under GEMM0. Sequential layers (overlap mined out).
// ---------------------------------------------------------------------------

#define N_NODES 50000
#define N_EDGES 800000

__device__ __half  g_bufA[N_NODES * 128];
__device__ __half  g_bufB[N_NODES * 128];
__device__ __half  g_bufC[N_NODES * 128];
__device__ int     g_deg[N_NODES];
__device__ int     g_indptr[N_NODES + 1];
__device__ int     g_cursor[N_NODES];
__device__ float2  g_edges[N_EDGES];   // {src (bit-cast int), weight}

// ---------------------------------------------------------------------------
__device__ __forceinline__ uint32_t pack_h2(float a, float b) {
    __half2 h = __floats2half2_rn(a, b);
    return *reinterpret_cast<uint32_t*>(&h);
}
__device__ __forceinline__ float2 unpack_h2(uint32_t w) {
    __half2 h = *reinterpret_cast<__half2*>(&w);
    return __half22float2(h);
}
__device__ __forceinline__ void mma_f16(
    float& d0, float& d1, float& d2, float& d3,
    uint32_t a0, uint32_t a1, uint32_t a2, uint32_t a3,
    uint32_t b0, uint32_t b1)
{
    asm volatile(
        "mma.sync.aligned.m16n8k16.row.col.f32.f16.f16.f32 "
        "{%0,%1,%2,%3},{%4,%5,%6,%7},{%8,%9},{%0,%1,%2,%3};"
        : "+f"(d0), "+f"(d1), "+f"(d2), "+f"(d3)
        : "r"(a0), "r"(a1), "r"(a2), "r"(a3), "r"(b0), "r"(b1));
}

// ---------------------------------------------------------------------------
// GEMM: Y[N, BNT](fp16) = X[N, 128] @ W[128, BNT]
// X is fp32 (XHALF=0, layer 0) or fp16 (XHALF=1).
// Block tile 64x64, 128 threads (4 warps, warp tile 32x32), KC=32 chunks.
// SMEM words are fp16x2 k-pairs; fragment indexing identical to the verified
// bf16 version (strides 20 / 72 words, conflict-free).
// ---------------------------------------------------------------------------
template <int BNT, int XHALF>
__global__ __launch_bounds__(128, 4) void gemm_f16_kernel(
    const void* __restrict__ Xv, const float* __restrict__ W,
    __half* __restrict__ Y, int N)
{
    constexpr int KC   = 32;
    constexpr int NK   = 128 / KC;
    constexpr int XSPW = 20;
    constexpr int WSPW = 72;

    __shared__ uint32_t Xs[64][XSPW];
    __shared__ uint32_t Ws[16][WSPW];

    const int tid  = threadIdx.x;
    const int lane = tid & 31;
    const int warp = tid >> 5;
    const int row0 = blockIdx.x * 64;
    const int nb   = blockIdx.y * 64;

    const int qr = lane >> 2;
    const int qt = lane & 3;
    const int wm = (warp & 1) * 32;
    const int wn = (warp >> 1) * 32;

    const float4* X4f = (const float4*)Xv;   // fp32 path
    const uint4*  X4h = (const uint4*)Xv;    // fp16 path (8 halves per uint4)
    const float4* W4  = (const float4*)W;

    float4 xrf[4];    // fp32 staging regs
    uint4  xrh[2];    // fp16 staging regs
    float4 wrA[2], wrB[2];

    auto ldgX = [&](int ch) {
        if (XHALF) {
#pragma unroll
            for (int i = 0; i < 2; i++) {
                int idx = tid + i * 128;            // 64 rows * 4 uint4
                int r = idx >> 2, c4 = idx & 3;
                int gr = row0 + r;
                xrh[i] = (gr < N) ? X4h[gr * 16 + ch * 4 + c4]
                                  : make_uint4(0, 0, 0, 0);
            }
        } else {
#pragma unroll
            for (int i = 0; i < 4; i++) {
                int idx = tid + i * 128;            // 64 rows * 8 float4
                int r = idx >> 3, c4 = idx & 7;
                int gr = row0 + r;
                xrf[i] = (gr < N) ? X4f[gr * 32 + ch * 8 + c4]
                                  : make_float4(0.f, 0.f, 0.f, 0.f);
            }
        }
    };
    auto ldgW = [&](int ch) {
#pragma unroll
        for (int i = 0; i < 2; i++) {
            int idx = tid + i * 128;                // 16 kpairs * 16 col4
            int kp = idx >> 4, cc = idx & 15;
            wrA[i] = W4[(((ch * KC + 2 * kp)     * BNT + nb) >> 2) + cc];
            wrB[i] = W4[(((ch * KC + 2 * kp + 1) * BNT + nb) >> 2) + cc];
        }
    };
    auto stsX = [&]() {
        if (XHALF) {
#pragma unroll
            for (int i = 0; i < 2; i++) {
                int idx = tid + i * 128;
                int r = idx >> 2, c4 = idx & 3;
                Xs[r][c4 * 4 + 0] = xrh[i].x;
                Xs[r][c4 * 4 + 1] = xrh[i].y;
                Xs[r][c4 * 4 + 2] = xrh[i].z;
                Xs[r][c4 * 4 + 3] = xrh[i].w;
            }
        } else {
#pragma unroll
            for (int i = 0; i < 4; i++) {
                int idx = tid + i * 128;
                int r = idx >> 3, c4 = idx & 7;
                Xs[r][c4 * 2 + 0] = pack_h2(xrf[i].x, xrf[i].y);
                Xs[r][c4 * 2 + 1] = pack_h2(xrf[i].z, xrf[i].w);
            }
        }
    };
    auto stsW = [&]() {
#pragma unroll
        for (int i = 0; i < 2; i++) {
            int idx = tid + i * 128;
            int kp = idx >> 4, cc = idx & 15;
            const float* a = (const float*)&wrA[i];
            const float* b = (const float*)&wrB[i];
#pragma unroll
            for (int j = 0; j < 4; j++)
                Ws[kp][cc * 4 + j] = pack_h2(a[j], b[j]);   // (k even, k odd)
        }
    };

    float acc[2][4][4] = {};

    ldgX(0); ldgW(0);
    stsX(); stsW();
    __syncthreads();

#pragma unroll
    for (int ch = 0; ch < NK; ch++) {
        if (ch + 1 < NK) { ldgX(ch + 1); ldgW(ch + 1); }

#pragma unroll
        for (int ks = 0; ks < 2; ks++) {            // two k16 steps per chunk
            const int kw = ks * 8 + qt;

            uint32_t a[2][4];
#pragma unroll
            for (int mt = 0; mt < 2; mt++) {
                int r = wm + mt * 16 + qr;
                a[mt][0] = Xs[r][kw];
                a[mt][1] = Xs[r + 8][kw];
                a[mt][2] = Xs[r][kw + 4];
                a[mt][3] = Xs[r + 8][kw + 4];
            }
            uint32_t b[4][2];
#pragma unroll
            for (int nt = 0; nt < 4; nt++) {
                int c = wn + nt * 8 + qr;
                b[nt][0] = Ws[ks * 8 + qt][c];
                b[nt][1] = Ws[ks * 8 + qt + 4][c];
            }
#pragma unroll
            for (int mt = 0; mt < 2; mt++)
#pragma unroll
                for (int nt = 0; nt < 4; nt++) {
                    float* d = acc[mt][nt];
                    mma_f16(d[0], d[1], d[2], d[3],
                            a[mt][0], a[mt][1], a[mt][2], a[mt][3],
                            b[nt][0], b[nt][1]);
                }
        }

        if (ch + 1 < NK) {
            __syncthreads();
            stsX(); stsW();
            __syncthreads();
        }
    }

    // Epilogue: pack fp32 acc -> fp16 pairs
    uint32_t* Y32 = (uint32_t*)Y;
#pragma unroll
    for (int mt = 0; mt < 2; mt++) {
#pragma unroll
        for (int nt = 0; nt < 4; nt++) {
            int gc = nb + wn + nt * 8 + qt * 2;     // even
            int r0g = row0 + wm + mt * 16 + qr;
            if (r0g < N)
                Y32[(r0g * BNT + gc) >> 1] = pack_h2(acc[mt][nt][0], acc[mt][nt][1]);
            int r1g = r0g + 8;
            if (r1g < N)
                Y32[(r1g * BNT + gc) >> 1] = pack_h2(acc[mt][nt][2], acc[mt][nt][3]);
        }
    }
}

// ---------------------------------------------------------------------------
// CSR build
// ---------------------------------------------------------------------------
__global__ __launch_bounds__(256) void hist_kernel(
    const int* __restrict__ dst, int* __restrict__ deg, int E)
{
    int e = blockIdx.x * blockDim.x + threadIdx.x;
    if (e < E) atomicAdd(&deg[__ldg(&dst[e])], 1);
}

__global__ __launch_bounds__(1024) void scan_kernel(
    const int* __restrict__ deg, int* __restrict__ indptr,
    int* __restrict__ cursor)
{
    __shared__ int sh[1024];
    const int CHUNK = (N_NODES + 1023) / 1024;
    int t = threadIdx.x;
    int begin = t * CHUNK;
    int end   = begin + CHUNK; if (end > N_NODES) end = N_NODES;

    int s = 0;
    for (int i = begin; i < end; i++) s += deg[i];
    sh[t] = s;
    __syncthreads();

    for (int off = 1; off < 1024; off <<= 1) {
        int v = sh[t];
        int a = (t >= off) ? sh[t - off] : 0;
        __syncthreads();
        sh[t] = v + a;
        __syncthreads();
    }

    int run = (t == 0) ? 0 : sh[t - 1];
    for (int i = begin; i < end; i++) {
        indptr[i] = run;
        cursor[i] = run;
        run += deg[i];
    }
    if (t == 1023) indptr[N_NODES] = run;
}

__global__ __launch_bounds__(256) void place_kernel(
    const int* __restrict__ src, const int* __restrict__ dst,
    const float* __restrict__ ew, int* __restrict__ cursor,
    float2* __restrict__ edges, int E)
{
    int e = blockIdx.x * blockDim.x + threadIdx.x;
    if (e >= E) return;
    int d = __ldg(&dst[e]);
    int p = atomicAdd(&cursor[d], 1);
    edges[p] = make_float2(__int_as_float(__ldg(&src[e])), __ldg(&ew[e]));
}

// ---------------------------------------------------------------------------
// Gather-aggregate, D=128 (fp16 rows): one warp per node, lane = 4 elements.
// MODE 0: val=acc+b; out0=val; out1=val+relu(val)    (layer 0)
// MODE 1: val=acc+b; out0=Bres+relu(val)             (layer 1)
// ---------------------------------------------------------------------------
__device__ __forceinline__ void acc_edge128(float4& acc, uint2 u, float w) {
    float2 f0 = unpack_h2(u.x);
    float2 f1 = unpack_h2(u.y);
    acc.x = fmaf(f0.x, w, acc.x); acc.y = fmaf(f0.y, w, acc.y);
    acc.z = fmaf(f1.x, w, acc.z); acc.w = fmaf(f1.y, w, acc.w);
}

template <int MODE>
__global__ __launch_bounds__(256) void gather128_kernel(
    const __half* __restrict__ H, const float2* __restrict__ edges,
    const int* __restrict__ indptr,
    const float* __restrict__ bias, const __half* __restrict__ Bres,
    __half* __restrict__ out0, __half* __restrict__ out1)
{
    int node = (blockIdx.x * 256 + threadIdx.x) >> 5;
    int lane = threadIdx.x & 31;
    if (node >= N_NODES) return;

    int start = __ldg(&indptr[node]);
    int endp  = __ldg(&indptr[node + 1]);
    int cnt   = endp - start;
    int last  = endp - 1;

    float4 acc = make_float4(0.f, 0.f, 0.f, 0.f);
    const uint2* H2 = (const uint2*)H;   // row = 32 uint2 (128 halves)

    if (cnt > 0) {
        float2 e0 = __ldg(&edges[start]);
        float2 e1 = __ldg(&edges[min(start + 1, last)]);
        int j = 0;
        for (; j + 1 < cnt; j += 2) {
            float2 n0 = __ldg(&edges[min(start + j + 2, last)]);
            float2 n1 = __ldg(&edges[min(start + j + 3, last)]);
            uint2 v0 = __ldg(&H2[(__float_as_int(e0.x) << 5) + lane]);
            uint2 v1 = __ldg(&H2[(__float_as_int(e1.x) << 5) + lane]);
            acc_edge128(acc, v0, e0.y);
            acc_edge128(acc, v1, e1.y);
            e0 = n0; e1 = n1;
        }
        if (j < cnt) {
            uint2 v0 = __ldg(&H2[(__float_as_int(e0.x) << 5) + lane]);
            acc_edge128(acc, v0, e0.y);
        }
    }

    float4 bb = ((const float4*)bias)[lane];
    float4 val = make_float4(acc.x + bb.x, acc.y + bb.y,
                             acc.z + bb.z, acc.w + bb.w);
    int idx = (node << 5) + lane;

    if (MODE == 0) {
        uint2 ov;
        ov.x = pack_h2(val.x, val.y);
        ov.y = pack_h2(val.z, val.w);
        ((uint2*)out0)[idx] = ov;
        uint2 oc;
        oc.x = pack_h2(val.x + fmaxf(val.x, 0.f), val.y + fmaxf(val.y, 0.f));
        oc.y = pack_h2(val.z + fmaxf(val.z, 0.f), val.w + fmaxf(val.w, 0.f));
        ((uint2*)out1)[idx] = oc;
    } else {
        uint2 bu = __ldg(&((const uint2*)Bres)[idx]);
        float2 b0 = unpack_h2(bu.x);
        float2 b1 = unpack_h2(bu.y);
        uint2 oc;
        oc.x = pack_h2(b0.x + fmaxf(val.x, 0.f), b0.y + fmaxf(val.y, 0.f));
        oc.y = pack_h2(b1.x + fmaxf(val.z, 0.f), b1.y + fmaxf(val.w, 0.f));
        ((uint2*)out0)[idx] = oc;
    }
}

// D=64 (fp16 rows), fp32 output: half-warp per node, lane = 4 elements.
__global__ __launch_bounds__(256) void gather64_kernel(
    const __half* __restrict__ H, const float2* __restrict__ edges,
    const int* __restrict__ indptr,
    const float* __restrict__ bias, float* __restrict__ out)
{
    int node = (blockIdx.x * 256 + threadIdx.x) >> 4;
    int lane = threadIdx.x & 15;
    if (node >= N_NODES) return;

    int start = __ldg(&indptr[node]);
    int endp  = __ldg(&indptr[node + 1]);
    int cnt   = endp - start;
    int last  = endp - 1;

    float4 acc = make_float4(0.f, 0.f, 0.f, 0.f);
    const uint2* H2 = (const uint2*)H;   // row = 16 uint2 (64 halves)

    if (cnt > 0) {
        float2 e0 = __ldg(&edges[start]);
        float2 e1 = __ldg(&edges[min(start + 1, last)]);
        int j = 0;
        for (; j + 1 < cnt; j += 2) {
            float2 n0 = __ldg(&edges[min(start + j + 2, last)]);
            float2 n1 = __ldg(&edges[min(start + j + 3, last)]);
            uint2 v0 = __ldg(&H2[(__float_as_int(e0.x) << 4) + lane]);
            uint2 v1 = __ldg(&H2[(__float_as_int(e1.x) << 4) + lane]);
            acc_edge128(acc, v0, e0.y);
            acc_edge128(acc, v1, e1.y);
            e0 = n0; e1 = n1;
        }
        if (j < cnt) {
            uint2 v0 = __ldg(&H2[(__float_as_int(e0.x) << 4) + lane]);
            acc_edge128(acc, v0, e0.y);
        }
    }

    float4 bb = ((const float4*)bias)[lane];
    ((float4*)out)[(node << 4) + lane] =
        make_float4(acc.x + bb.x, acc.y + bb.y, acc.z + bb.z, acc.w + bb.w);
}

// ---------------------------------------------------------------------------

extern "C" void kernel_launch(void* const* d_in, const int* in_sizes, int n_in,
                              void* d_out, int out_size)
{
    const float* x  = (const float*)d_in[0];
    const int*   ei = (const int*)d_in[1];
    const float* ea = (const float*)d_in[2];
    const float* W1 = (const float*)d_in[3];
    const float* b1 = (const float*)d_in[4];
    const float* W2 = (const float*)d_in[5];
    const float* b2 = (const float*)d_in[6];
    const float* W3 = (const float*)d_in[7];
    const float* b3 = (const float*)d_in[8];
    float* out = (float*)d_out;

    const int N = N_NODES;
    const int E = N_EDGES;
    const int* src = ei;
    const int* dst = ei + E;

    __half *A, *B, *C;
    int *deg, *indptr, *cursor;
    float2* edges;
    cudaGetSymbolAddress((void**)&A, g_bufA);
    cudaGetSymbolAddress((void**)&B, g_bufB);
    cudaGetSymbolAddress((void**)&C, g_bufC);
    cudaGetSymbolAddress((void**)&deg, g_deg);
    cudaGetSymbolAddress((void**)&indptr, g_indptr);
    cudaGetSymbolAddress((void**)&cursor, g_cursor);
    cudaGetSymbolAddress((void**)&edges, g_edges);

    const int e_blocks    = (E + 255) / 256;
    const int g128_blocks = (N * 32 + 255) / 256;
    const int g64_blocks  = (N * 16 + 255) / 256;
    const int mrows       = (N + 63) / 64;          // 782

    dim3 grid128(mrows, 2);
    dim3 grid64(mrows, 1);

    // Side stream + events (host objects; per call)
    cudaStream_t s2;
    cudaStreamCreateWithFlags(&s2, cudaStreamNonBlocking);
    cudaEvent_t evFork, evJoin;
    cudaEventCreateWithFlags(&evFork, cudaEventDisableTiming);
    cudaEventCreateWithFlags(&evJoin, cudaEventDisableTiming);

    // --- Fork: CSR build on s2 ∥ GEMM0 on main ---
    cudaEventRecord(evFork, 0);
    cudaStreamWaitEvent(s2, evFork, 0);

    cudaMemsetAsync(deg, 0, N * sizeof(int), s2);
    hist_kernel<<<e_blocks, 256, 0, s2>>>(dst, deg, E);
    scan_kernel<<<1, 1024, 0, s2>>>(deg, indptr, cursor);
    place_kernel<<<e_blocks, 256, 0, s2>>>(src, dst, ea, cursor, edges, E);
    cudaEventRecord(evJoin, s2);

    gemm_f16_kernel<128, 0><<<grid128, 128>>>(x, W1, A, N);   // fp32 input

    cudaStreamWaitEvent(0, evJoin, 0);

    // --- Layer 0: B = x1 = agg(x@W1)+b1 ; C = x1 + relu(x1) ---
    gather128_kernel<0><<<g128_blocks, 256>>>(A, edges, indptr, b1, nullptr, B, C);

    // --- Layer 1: C = x1 + relu(agg(C@W2)+b2) ---
    gemm_f16_kernel<128, 1><<<grid128, 128>>>(C, W2, A, N);
    gather128_kernel<1><<<g128_blocks, 256>>>(A, edges, indptr, b2, B, C, nullptr);

    // --- Layer 2: out = agg(C@W3)+b3 ---
    gemm_f16_kernel<64, 1><<<grid64, 128>>>(C, W3, A, N);
    gather64_kernel<<<g64_blocks, 256>>>(A, edges, indptr, b3, out);
}